// round 14
// baseline (speedup 1.0000x reference)
#include <cuda_runtime.h>
#include <cuda_bf16.h>
#include <math.h>
#include <stdint.h>

#define NV 50000
#define NE 300
#define NF 300
#define NSENT 1024
#define SLEN 128
#define QLEN 32

// Device-global scratch — ~231KB (guard-safe, verified many rounds).
__device__ float g_B2t[128 * 304];   // [c][304]: c<32 = q_emb; 32+32k+q = U_k[q]
__device__ float g_qemb[QLEN * NE];
__device__ float g_qconv[QLEN * NF];
__device__ float g_invq[64];         // [0..31]=1/|q_emb|, [32..63]=1/|q_conv|

// ---------------------------------------------------------------------------
__device__ __forceinline__ uint32_t smem_u32(const void* p) {
    return (uint32_t)__cvta_generic_to_shared(p);
}

#define LDSM_X4(r0, r1, r2, r3, a) \
    asm volatile("ldmatrix.sync.aligned.m8n8.x4.shared.b16 {%0,%1,%2,%3}, [%4];" \
                 : "=r"(r0), "=r"(r1), "=r"(r2), "=r"(r3) : "r"(a))

#define MMA16816(d, a0, a1, a2, a3, b0, b1) \
    asm volatile("mma.sync.aligned.m16n8k16.row.col.f32.bf16.bf16.f32 " \
                 "{%0,%1,%2,%3}, {%4,%5,%6,%7}, {%8,%9}, {%0,%1,%2,%3};" \
                 : "+f"((d)[0]), "+f"((d)[1]), "+f"((d)[2]), "+f"((d)[3]) \
                 : "r"(a0), "r"(a1), "r"(a2), "r"(a3), "r"(b0), "r"(b1))

__device__ __forceinline__ uint2 pack_bf16x4(float4 v) {
    __nv_bfloat162 lo = __floats2bfloat162_rn(v.x, v.y);
    __nv_bfloat162 hi = __floats2bfloat162_rn(v.z, v.w);
    uint2 r;
    r.x = *(uint32_t*)&lo;
    r.y = *(uint32_t*)&hi;
    return r;
}

// ---------------------------------------------------------------------------
// Prep kernels (proven)
__global__ void k_prep_q(const float* __restrict__ embeds, const int* __restrict__ question) {
    int q = blockIdx.x;
    int tid = threadIdx.x;
    int tok = question[q];
    const float* src = embeds + (size_t)tok * NE;
    float ss = 0.f;
    for (int e = tid; e < NE; e += 128) {
        float v = src[e];
        g_qemb[q * NE + e] = v;
        g_B2t[q * 304 + e] = v;
        ss += v * v;
    }
    __shared__ float red[128];
    red[tid] = ss;
    __syncthreads();
    for (int o = 64; o > 0; o >>= 1) {
        if (tid < o) red[tid] += red[tid + o];
        __syncthreads();
    }
    if (tid == 0) g_invq[q] = rsqrtf(red[0]);
}

__global__ void k_qconv(const float* __restrict__ filters) {
    int q = blockIdx.x;
    int f = blockIdx.y * 128 + threadIdx.x;
    if (f >= NF) return;
    float acc = 0.f;
    for (int k = 0; k < 3; k++) {
        if (q + k >= QLEN) break;
        const float* w = filters + (size_t)f * 900 + k * 300;
        const float* x = g_qemb + (q + k) * NE;
        #pragma unroll 4
        for (int e = 0; e < NE; e++) acc += x[e] * w[e];
    }
    g_qconv[q * NF + f] = acc;
}

__global__ void k_buildU(const float* __restrict__ filters) {
    __shared__ float red[128];
    int c = blockIdx.x;
    int k = c >> 5, q = c & 31;
    int e = blockIdx.y * 100 + threadIdx.x;
    if (threadIdx.x < 100) {
        const float* qc = g_qconv + q * NF;
        const float* fb = filters + k * 300 + e;
        float a0 = 0.f, a1 = 0.f, a2 = 0.f, a3 = 0.f;
        for (int f = 0; f < NF; f += 4) {
            a0 += fb[(size_t)(f + 0) * 900] * qc[f + 0];
            a1 += fb[(size_t)(f + 1) * 900] * qc[f + 1];
            a2 += fb[(size_t)(f + 2) * 900] * qc[f + 2];
            a3 += fb[(size_t)(f + 3) * 900] * qc[f + 3];
        }
        g_B2t[(32 + c) * 304 + e] = (a0 + a1) + (a2 + a3);
    }
    if (blockIdx.y == 0 && blockIdx.x < 32) {
        int qq = blockIdx.x;
        int tid = threadIdx.x;
        float ss = 0.f;
        for (int f = tid; f < NF; f += 128) {
            float v = g_qconv[qq * NF + f];
            ss += v * v;
        }
        red[tid] = ss;
        __syncthreads();
        for (int o = 64; o > 0; o >>= 1) {
            if (tid < o) red[tid] += red[tid + o];
            __syncthreads();
        }
        if (tid == 0) g_invq[32 + qq] = rsqrtf(red[0]);
    }
}

// ---------------------------------------------------------------------------
// top-5 over 4 register values per lane (128 values per warp)
__device__ __forceinline__ void top5v(float v0, float v1, float v2, float v3,
                                      int lane, float& mx, float& mean5) {
    float v[4] = {v0, v1, v2, v3};
    float summ = 0.f;
    mx = 0.f;
    #pragma unroll
    for (int r = 0; r < 5; r++) {
        float bv = v[0];
        int bj = 0;
        #pragma unroll
        for (int j = 1; j < 4; j++)
            if (v[j] > bv) { bv = v[j]; bj = j; }
        float cv = bv;
        int cid = (lane << 2) | bj;
        #pragma unroll
        for (int o = 16; o > 0; o >>= 1) {
            float ov = __shfl_down_sync(0xffffffffu, cv, o);
            int oi = __shfl_down_sync(0xffffffffu, cid, o);
            if (ov > cv || (ov == cv && oi < cid)) { cv = ov; cid = oi; }
        }
        cv = __shfl_sync(0xffffffffu, cv, 0);
        cid = __shfl_sync(0xffffffffu, cid, 0);
        summ += cv;
        if (r == 0) mx = cv;
        if ((cid >> 2) == lane) {
            #pragma unroll
            for (int j = 0; j < 4; j++)
                if ((cid & 3) == j) v[j] = -INFINITY;
        }
    }
    mean5 = summ * 0.2f;
}

// ---------------------------------------------------------------------------
// Fused kernel: TWO sentences per block, 512 threads, double-buffered W slab.
// W / B2 staging amortized over 2 sentences; stage(r+1) overlaps mma(r).
#define EROW 312                  // bf16 row stride (conflict-free, proven)
#define ERN  130                  // 128 rows + 2 zero lookahead
#define TILE_B (ERN * EROW * 2)            // 81120 bytes per sentence tile
#define OFF_E    0
#define SZ_E     (2 * TILE_B)              // 162240
#define OFF_W    SZ_E                      // double buffer, 2 x 19968
#define SZ_W1    (32 * EROW * 2)
#define OFF_IDS  (OFF_W + 2 * SZ_W1)       // 202176 (256 ints)
#define OFF_INVI (OFF_IDS + 1024)          // 256 floats
#define OFF_INVS (OFF_INVI + 1024)         // 256 floats
#define OFF_QV   (OFF_INVS + 1024)         // qinvI[32] qinvS[32] qmf[32] slog[64]
#define DOC_SMEM (OFF_QV + 640)            // 205888
#define PSTRIDE  132
#define PTILE    (128 * PSTRIDE)           // floats per sentence P plane

__device__ __forceinline__ void stage_w(const float* __restrict__ filters,
                                        __nv_bfloat16* dst, int slab, int tap, int tid) {
    for (int i = tid; i < 32 * 76; i += 512) {
        int fl = i / 76, e4 = i - fl * 76;
        int f = slab * 32 + fl;
        float4 v = make_float4(0.f, 0.f, 0.f, 0.f);
        if (e4 < 75 && f < NF)
            v = *(const float4*)(filters + (size_t)f * 900 + tap * 300 + e4 * 4);
        *(uint2*)&dst[fl * EROW + e4 * 4] = pack_bf16x4(v);
    }
}

__device__ __forceinline__ void stage_b(__nv_bfloat16* dst, int cs, int tid) {
    for (int i = tid; i < 32 * 76; i += 512) {
        int cl = i / 76, e4 = i - cl * 76;
        float4 v = make_float4(0.f, 0.f, 0.f, 0.f);
        if (e4 < 75)
            v = *(const float4*)(g_B2t + (size_t)(cs * 32 + cl) * 304 + e4 * 4);
        *(uint2*)&dst[cl * EROW + e4 * 4] = pack_bf16x4(v);
    }
}

__global__ void __launch_bounds__(512, 1) k_doc(const float* __restrict__ embeds,
                                                const float* __restrict__ filters,
                                                const int* __restrict__ doc1,
                                                const int* __restrict__ doc2,
                                                const float* __restrict__ dsim1,
                                                const float* __restrict__ dsim2,
                                                const int* __restrict__ question,
                                                const float* __restrict__ lin_w,
                                                const float* __restrict__ lin_b,
                                                float* __restrict__ out) {
    extern __shared__ unsigned char smem[];
    __nv_bfloat16* Eb = (__nv_bfloat16*)(smem + OFF_E);
    __nv_bfloat16* Ws0 = (__nv_bfloat16*)(smem + OFF_W);
    __nv_bfloat16* Ws1 = (__nv_bfloat16*)(smem + OFF_W + SZ_W1);
    int*   ids    = (int*)(smem + OFF_IDS);
    float* invI_s = (float*)(smem + OFF_INVI);
    float* invS_s = (float*)(smem + OFF_INVS);
    float* qinvI  = (float*)(smem + OFF_QV);
    float* qinvS  = qinvI + 32;
    float* qmf    = qinvS + 32;
    float* slog   = qmf + 32;
    float* Pbase  = (float*)(smem + OFF_E);   // alias: E dead before P written

    int bn = blockIdx.x;                       // 0..1023; sentences 2bn, 2bn+1
    const int* doc = (bn < 512) ? doc1 : doc2;
    const float* dsim = (bn < 512) ? dsim1 : dsim2;
    int m0 = (bn < 512) ? 2 * bn : 2 * bn - NSENT;   // within-doc sentence idx

    int tid = threadIdx.x, lane = tid & 31, wid = tid >> 5;
    int g2 = lane >> 2, c4 = lane & 3;
    int t8 = lane >> 3, rr = lane & 7;
    int arow = (t8 & 1) * 8 + rr;
    int acol = (t8 >> 1) * 8;
    int brow = (t8 >> 1) * 8 + rr;
    int bcol = (t8 & 1) * 8;
    int tile = wid >> 3;                       // 0 or 1: which sentence
    int mbase = (wid & 7) * 16;                // rows within sentence tile

    // ---- phase 0: zero E, ids + q constants ----
    {
        uint32_t* z = (uint32_t*)(smem + OFF_E);
        for (int i = tid; i < SZ_E / 4; i += 512) z[i] = 0u;
    }
    if (tid < 256) {
        int j = tid >> 7, s = tid & 127;
        ids[tid] = doc[(size_t)(m0 + j) * SLEN + s];
    }
    if (tid < QLEN) {
        qmf[tid] = (question[tid] > 1) ? 1.f : 0.f;
        qinvI[tid] = g_invq[tid];
        qinvS[tid] = g_invq[32 + tid];
    }
    __syncthreads();

    // ---- phase 1: gather E (both tiles) -> bf16 + invI ----
    for (int sg = wid; sg < 256; sg += 16) {
        int tl = sg >> 7, s = sg & 127;
        const float4* row = (const float4*)(embeds + (size_t)ids[sg] * NE);
        __nv_bfloat16* dst = Eb + tl * (TILE_B / 2) + s * EROW;
        float ss = 0.f;
        for (int e4 = lane; e4 < 75; e4 += 32) {
            float4 v = row[e4];
            *(uint2*)&dst[e4 * 4] = pack_bf16x4(v);
            ss += v.x * v.x + v.y * v.y + v.z * v.z + v.w * v.w;
        }
        #pragma unroll
        for (int o = 16; o > 0; o >>= 1) ss += __shfl_down_sync(0xffffffffu, ss, o);
        if (lane == 0) invI_s[sg] = rsqrtf(ss);
    }

    uint32_t eh_u = smem_u32(Eb) + tile * TILE_B + mbase * EROW * 2;
    uint32_t wsu[2] = {smem_u32(Ws0), smem_u32(Ws1)};
    __nv_bfloat16* wsp[2] = {Ws0, Ws1};

    // ---- phase 2: conv norms; 30 rounds, double-buffered staging ----
    stage_w(filters, Ws0, 0, 0, tid);
    __syncthreads();

    float rs0 = 0.f, rs1 = 0.f;
    float cc[4][4];
    for (int r = 0; r < 30; r++) {
        int tap = r % 3;
        int buf = r & 1;
        if (r < 29) {
            int rn = r + 1;
            stage_w(filters, wsp[buf ^ 1], rn / 3, rn % 3, tid);
        }
        if (tap == 0) {
            #pragma unroll
            for (int j = 0; j < 4; j++)
                #pragma unroll
                for (int x = 0; x < 4; x++) cc[j][x] = 0.f;
        }
        uint32_t wu = wsu[buf];
        for (int ec = 0; ec < 19; ec++) {
            uint32_t a0, a1, a2, a3;
            uint32_t aaddr = eh_u + (uint32_t)(((tap + arow) * EROW + ec * 16 + acol) * 2);
            LDSM_X4(a0, a1, a2, a3, aaddr);
            #pragma unroll
            for (int np = 0; np < 2; np++) {
                uint32_t b0, b1, b2, b3;
                uint32_t baddr = wu + (uint32_t)(((np * 16 + brow) * EROW + ec * 16 + bcol) * 2);
                LDSM_X4(b0, b1, b2, b3, baddr);
                MMA16816(cc[np * 2], a0, a1, a2, a3, b0, b1);
                MMA16816(cc[np * 2 + 1], a0, a1, a2, a3, b2, b3);
            }
        }
        if (tap == 2) {
            #pragma unroll
            for (int j = 0; j < 4; j++) {
                rs0 += cc[j][0] * cc[j][0] + cc[j][1] * cc[j][1];
                rs1 += cc[j][2] * cc[j][2] + cc[j][3] * cc[j][3];
            }
        }
        __syncthreads();
    }
    rs0 += __shfl_xor_sync(0xffffffffu, rs0, 1);
    rs0 += __shfl_xor_sync(0xffffffffu, rs0, 2);
    rs1 += __shfl_xor_sync(0xffffffffu, rs1, 1);
    rs1 += __shfl_xor_sync(0xffffffffu, rs1, 2);
    if (c4 == 0) {
        invS_s[wid * 16 + g2] = rsqrtf(rs0);       // wid*16+g2 == tile*128 + mbase + g2
        invS_s[wid * 16 + g2 + 8] = rsqrtf(rs1);
    }

    // ---- phase 3: P = E @ B2t, 4 c-slabs, double-buffered ----
    float pa[4][4][4];
    #pragma unroll
    for (int cs = 0; cs < 4; cs++)
        #pragma unroll
        for (int nt = 0; nt < 4; nt++)
            #pragma unroll
            for (int x = 0; x < 4; x++) pa[cs][nt][x] = 0.f;

    stage_b(Ws0, 0, tid);
    __syncthreads();
    for (int cs = 0; cs < 4; cs++) {
        int buf = cs & 1;
        if (cs < 3) stage_b(wsp[buf ^ 1], cs + 1, tid);
        uint32_t wu = wsu[buf];
        for (int ec = 0; ec < 19; ec++) {
            uint32_t a0, a1, a2, a3;
            uint32_t aaddr = eh_u + (uint32_t)((arow * EROW + ec * 16 + acol) * 2);
            LDSM_X4(a0, a1, a2, a3, aaddr);
            #pragma unroll
            for (int np = 0; np < 2; np++) {
                uint32_t b0, b1, b2, b3;
                uint32_t baddr = wu + (uint32_t)(((np * 16 + brow) * EROW + ec * 16 + bcol) * 2);
                LDSM_X4(b0, b1, b2, b3, baddr);
                MMA16816(pa[cs][np * 2], a0, a1, a2, a3, b0, b1);
                MMA16816(pa[cs][np * 2 + 1], a0, a1, a2, a3, b2, b3);
            }
        }
        __syncthreads();   // staging done AND (on last iter) all E reads done
    }

    // ---- store P[c][s] per sentence (aliases dead E region) ----
    float* P = Pbase + tile * PTILE;
    #pragma unroll
    for (int cs = 0; cs < 4; cs++)
        #pragma unroll
        for (int nt = 0; nt < 4; nt++) {
            int c = cs * 32 + nt * 8 + c4 * 2;
            int s = mbase + g2;
            P[c * PSTRIDE + s] = pa[cs][nt][0];
            P[(c + 1) * PSTRIDE + s] = pa[cs][nt][1];
            P[c * PSTRIDE + s + 8] = pa[cs][nt][2];
            P[(c + 1) * PSTRIDE + s + 8] = pa[cs][nt][3];
        }
    __syncthreads();

    // ---- phase 4/5: sims -> top-5 -> logit ----
    float w0 = lin_w[0], w1 = lin_w[1], w2 = lin_w[2];
    float w3 = lin_w[3], w4 = lin_w[4], w5 = lin_w[5], b0 = lin_b[0];
    {
        int sent = tile;                 // warps 0-7 -> sentence 0, 8-15 -> 1
        int sb = sent * 128;
        float* Ps = Pbase + sent * PTILE;
        for (int qq = (wid & 7) * 4; qq < (wid & 7) * 4 + 4; qq++) {
            float qi = qinvI[qq], qs = qinvS[qq], qm = qmf[qq];
            float vI[4], vS[4], vO[4];
            #pragma unroll
            for (int j = 0; j < 4; j++) {
                int s = lane + 32 * j;
                float a = Ps[qq * PSTRIDE + s] * qi * invI_s[sb + s] * qm;
                if (ids[sb + s] <= 1) a = 0.f;
                vI[j] = a;
                float num = Ps[(32 + qq) * PSTRIDE + s];
                if (s + 1 < SLEN) num += Ps[(64 + qq) * PSTRIDE + s + 1];
                if (s + 2 < SLEN) num += Ps[(96 + qq) * PSTRIDE + s + 2];
                vS[j] = num * qs * invS_s[sb + s];
                vO[j] = dsim[((size_t)(m0 + sent) * QLEN + qq) * SLEN + s];
            }
            float mI, aI, mS, aS, mO, aO;
            top5v(vI[0], vI[1], vI[2], vI[3], lane, mI, aI);
            top5v(vS[0], vS[1], vS[2], vS[3], lane, mS, aS);
            top5v(vO[0], vO[1], vO[2], vO[3], lane, mO, aO);
            float logit = b0 + w0 * mI + w1 * aI + w2 * mS + w3 * aS + w4 * mO + w5 * aO;
            if (lane == 0) slog[sent * 32 + qq] = 1.f / (1.f + expf(-logit));
        }
    }
    __syncthreads();

    if (wid < 2) {
        float v = slog[wid * 32 + lane];
        #pragma unroll
        for (int o = 16; o > 0; o >>= 1) v += __shfl_down_sync(0xffffffffu, v, o);
        if (lane == 0) out[2 * bn + wid] = v * (1.0f / QLEN);
    }
}

// ---------------------------------------------------------------------------
// Input order: embeds, filters, lin_w, lin_b, question, doc1, doc2,
//              doc1_sim, doc2_sim
extern "C" void kernel_launch(void* const* d_in, const int* in_sizes, int n_in,
                              void* d_out, int out_size) {
    const float* embeds   = (const float*)d_in[0];
    const float* filters  = (const float*)d_in[1];
    const float* lin_w    = (const float*)d_in[2];
    const float* lin_b    = (const float*)d_in[3];
    const int*   question = (const int*)d_in[4];
    const int*   doc1     = (const int*)d_in[5];
    const int*   doc2     = (const int*)d_in[6];
    const float* doc1_sim = (const float*)d_in[7];
    const float* doc2_sim = (const float*)d_in[8];
    float* out = (float*)d_out;

    cudaFuncSetAttribute(k_doc, cudaFuncAttributeMaxDynamicSharedMemorySize, DOC_SMEM);

    k_prep_q<<<QLEN, 128>>>(embeds, question);
    k_qconv<<<dim3(QLEN, 3), 128>>>(filters);
    k_buildU<<<dim3(96, 3), 128>>>(filters);

    k_doc<<<NSENT, 512, DOC_SMEM>>>(embeds, filters, doc1, doc2,
                                    doc1_sim, doc2_sim, question,
                                    lin_w, lin_b, out);
}

// round 15
// speedup vs baseline: 1.2938x; 1.2938x over previous
#include <cuda_runtime.h>
#include <cuda_bf16.h>
#include <math.h>
#include <stdint.h>

#define NV 50000
#define NE 300
#define NF 300
#define NSENT 1024
#define SLEN 128
#define QLEN 32

// Device-global scratch — ~231KB (guard-safe, verified many rounds).
__device__ float g_B2t[128 * 304];   // [c][304]: c<32 = q_emb; 32+32k+q = U_k[q]
__device__ float g_qemb[QLEN * NE];
__device__ float g_qconv[QLEN * NF];
__device__ float g_invq[64];         // [0..31]=1/|q_emb|, [32..63]=1/|q_conv|

// ---------------------------------------------------------------------------
__device__ __forceinline__ uint32_t smem_u32(const void* p) {
    return (uint32_t)__cvta_generic_to_shared(p);
}

#define LDSM_X4(r0, r1, r2, r3, a) \
    asm volatile("ldmatrix.sync.aligned.m8n8.x4.shared.b16 {%0,%1,%2,%3}, [%4];" \
                 : "=r"(r0), "=r"(r1), "=r"(r2), "=r"(r3) : "r"(a))

#define MMA16816(d, a0, a1, a2, a3, b0, b1) \
    asm volatile("mma.sync.aligned.m16n8k16.row.col.f32.bf16.bf16.f32 " \
                 "{%0,%1,%2,%3}, {%4,%5,%6,%7}, {%8,%9}, {%0,%1,%2,%3};" \
                 : "+f"((d)[0]), "+f"((d)[1]), "+f"((d)[2]), "+f"((d)[3]) \
                 : "r"(a0), "r"(a1), "r"(a2), "r"(a3), "r"(b0), "r"(b1))

__device__ __forceinline__ uint2 pack_bf16x4(float4 v) {
    __nv_bfloat162 lo = __floats2bfloat162_rn(v.x, v.y);
    __nv_bfloat162 hi = __floats2bfloat162_rn(v.z, v.w);
    uint2 r;
    r.x = *(uint32_t*)&lo;
    r.y = *(uint32_t*)&hi;
    return r;
}

// ---------------------------------------------------------------------------
// Prep kernels (proven)
__global__ void k_prep_q(const float* __restrict__ embeds, const int* __restrict__ question) {
    int q = blockIdx.x;
    int tid = threadIdx.x;
    int tok = question[q];
    const float* src = embeds + (size_t)tok * NE;
    float ss = 0.f;
    for (int e = tid; e < NE; e += 128) {
        float v = src[e];
        g_qemb[q * NE + e] = v;
        g_B2t[q * 304 + e] = v;
        ss += v * v;
    }
    __shared__ float red[128];
    red[tid] = ss;
    __syncthreads();
    for (int o = 64; o > 0; o >>= 1) {
        if (tid < o) red[tid] += red[tid + o];
        __syncthreads();
    }
    if (tid == 0) g_invq[q] = rsqrtf(red[0]);
}

__global__ void k_qconv(const float* __restrict__ filters) {
    int q = blockIdx.x;
    int f = blockIdx.y * 128 + threadIdx.x;
    if (f >= NF) return;
    float acc = 0.f;
    for (int k = 0; k < 3; k++) {
        if (q + k >= QLEN) break;
        const float* w = filters + (size_t)f * 900 + k * 300;
        const float* x = g_qemb + (q + k) * NE;
        #pragma unroll 4
        for (int e = 0; e < NE; e++) acc += x[e] * w[e];
    }
    g_qconv[q * NF + f] = acc;
}

__global__ void k_buildU(const float* __restrict__ filters) {
    __shared__ float red[128];
    int c = blockIdx.x;
    int k = c >> 5, q = c & 31;
    int e = blockIdx.y * 100 + threadIdx.x;
    if (threadIdx.x < 100) {
        const float* qc = g_qconv + q * NF;
        const float* fb = filters + k * 300 + e;
        float a0 = 0.f, a1 = 0.f, a2 = 0.f, a3 = 0.f;
        for (int f = 0; f < NF; f += 4) {
            a0 += fb[(size_t)(f + 0) * 900] * qc[f + 0];
            a1 += fb[(size_t)(f + 1) * 900] * qc[f + 1];
            a2 += fb[(size_t)(f + 2) * 900] * qc[f + 2];
            a3 += fb[(size_t)(f + 3) * 900] * qc[f + 3];
        }
        g_B2t[(32 + c) * 304 + e] = (a0 + a1) + (a2 + a3);
    }
    if (blockIdx.y == 0 && blockIdx.x < 32) {
        int qq = blockIdx.x;
        int tid = threadIdx.x;
        float ss = 0.f;
        for (int f = tid; f < NF; f += 128) {
            float v = g_qconv[qq * NF + f];
            ss += v * v;
        }
        red[tid] = ss;
        __syncthreads();
        for (int o = 64; o > 0; o >>= 1) {
            if (tid < o) red[tid] += red[tid + o];
            __syncthreads();
        }
        if (tid == 0) g_invq[32 + qq] = rsqrtf(red[0]);
    }
}

// ---------------------------------------------------------------------------
// top-5 over 4 register values per lane (128 values per warp)
__device__ __forceinline__ void top5v(float v0, float v1, float v2, float v3,
                                      int lane, float& mx, float& mean5) {
    float v[4] = {v0, v1, v2, v3};
    float summ = 0.f;
    mx = 0.f;
    #pragma unroll
    for (int r = 0; r < 5; r++) {
        float bv = v[0];
        int bj = 0;
        #pragma unroll
        for (int j = 1; j < 4; j++)
            if (v[j] > bv) { bv = v[j]; bj = j; }
        float cv = bv;
        int cid = (lane << 2) | bj;
        #pragma unroll
        for (int o = 16; o > 0; o >>= 1) {
            float ov = __shfl_down_sync(0xffffffffu, cv, o);
            int oi = __shfl_down_sync(0xffffffffu, cid, o);
            if (ov > cv || (ov == cv && oi < cid)) { cv = ov; cid = oi; }
        }
        cv = __shfl_sync(0xffffffffu, cv, 0);
        cid = __shfl_sync(0xffffffffu, cid, 0);
        summ += cv;
        if (r == 0) mx = cv;
        if ((cid >> 2) == lane) {
            #pragma unroll
            for (int j = 0; j < 4; j++)
                if ((cid & 3) == j) v[j] = -INFINITY;
        }
    }
    mean5 = summ * 0.2f;
}

// ---------------------------------------------------------------------------
// Fused kernel: 2 sentences/block, 512 threads. Warp tile = 32 M-rows x 32 N,
// N split across warp f-halves of a 64-wide slab -> 2.0 LDSM-wavefronts/mma
// (was 3.0), the binder per R13/R14 ncu (L1 pipe 60-70%).
#define EROW 312                  // bf16 row stride (conflict-free, proven)
#define ERN  130                  // 128 rows + 2 zero lookahead
#define TILE_B (ERN * EROW * 2)            // 81120 bytes per sentence tile
#define OFF_E    0
#define SZ_E     (2 * TILE_B)              // 162240
#define OFF_W    SZ_E                      // single 64-row slab
#define SZ_W     (64 * EROW * 2)           // 39936
#define OFF_IDS  (OFF_W + SZ_W)            // 202176 (256 ints)
#define OFF_INVI (OFF_IDS + 1024)
#define OFF_INVS (OFF_INVI + 1024)
#define OFF_PN   (OFF_INVS + 1024)         // pnorm[256][2] floats = 2048
#define OFF_QV   (OFF_PN + 2048)           // qinvI[32] qinvS[32] qmf[32] slog[64]
#define DOC_SMEM (OFF_QV + 640)            // 207936
#define PSTRIDE  132
#define PTILE    (128 * PSTRIDE)

// stage 64 filter rows (slab64*64 .. +64) for one tap
__device__ __forceinline__ void stage_w64(const float* __restrict__ filters,
                                          __nv_bfloat16* dst, int slab64, int tap, int tid) {
    for (int i = tid; i < 64 * 76; i += 512) {
        int fl = i / 76, e4 = i - fl * 76;
        int f = slab64 * 64 + fl;
        float4 v = make_float4(0.f, 0.f, 0.f, 0.f);
        if (e4 < 75 && f < NF)
            v = *(const float4*)(filters + (size_t)f * 900 + tap * 300 + e4 * 4);
        *(uint2*)&dst[fl * EROW + e4 * 4] = pack_bf16x4(v);
    }
}

// stage 64 B2t rows (rnd*64 .. +64)
__device__ __forceinline__ void stage_b64(__nv_bfloat16* dst, int rnd, int tid) {
    for (int i = tid; i < 64 * 76; i += 512) {
        int cl = i / 76, e4 = i - cl * 76;
        float4 v = make_float4(0.f, 0.f, 0.f, 0.f);
        if (e4 < 75)
            v = *(const float4*)(g_B2t + (size_t)(rnd * 64 + cl) * 304 + e4 * 4);
        *(uint2*)&dst[cl * EROW + e4 * 4] = pack_bf16x4(v);
    }
}

__global__ void __launch_bounds__(512, 1) k_doc(const float* __restrict__ embeds,
                                                const float* __restrict__ filters,
                                                const int* __restrict__ doc1,
                                                const int* __restrict__ doc2,
                                                const float* __restrict__ dsim1,
                                                const float* __restrict__ dsim2,
                                                const int* __restrict__ question,
                                                const float* __restrict__ lin_w,
                                                const float* __restrict__ lin_b,
                                                float* __restrict__ out) {
    extern __shared__ unsigned char smem[];
    __nv_bfloat16* Eb = (__nv_bfloat16*)(smem + OFF_E);
    __nv_bfloat16* Ws = (__nv_bfloat16*)(smem + OFF_W);
    int*   ids    = (int*)(smem + OFF_IDS);
    float* invI_s = (float*)(smem + OFF_INVI);
    float* invS_s = (float*)(smem + OFF_INVS);
    float* pnorm  = (float*)(smem + OFF_PN);
    float* qinvI  = (float*)(smem + OFF_QV);
    float* qinvS  = qinvI + 32;
    float* qmf    = qinvS + 32;
    float* slog   = qmf + 32;
    float* Pbase  = (float*)(smem + OFF_E);   // alias: E dead before P written

    int bn = blockIdx.x;                       // sentences 2bn, 2bn+1
    const int* doc = (bn < 512) ? doc1 : doc2;
    const float* dsim = (bn < 512) ? dsim1 : dsim2;
    int m0 = (bn < 512) ? 2 * bn : 2 * bn - NSENT;

    int tid = threadIdx.x, lane = tid & 31, wid = tid >> 5;
    int g2 = lane >> 2, c4 = lane & 3;
    int t8 = lane >> 3, rr = lane & 7;
    int arow = (t8 & 1) * 8 + rr;
    int acol = (t8 >> 1) * 8;
    int brow = (t8 >> 1) * 8 + rr;
    int bcol = (t8 & 1) * 8;

    int sent = wid >> 3;                       // 0/1
    int ww = wid & 7;
    int r0 = (ww & 3) * 32;                    // 32-row warp tile base
    int fhalf = ww >> 2;                       // 0/1: which 32 cols of 64-slab

    // ---- phase 0 ----
    {
        uint32_t* z = (uint32_t*)(smem + OFF_E);
        for (int i = tid; i < SZ_E / 4; i += 512) z[i] = 0u;
    }
    if (tid < 256) {
        int j = tid >> 7, s = tid & 127;
        ids[tid] = doc[(size_t)(m0 + j) * SLEN + s];
    }
    if (tid < QLEN) {
        qmf[tid] = (question[tid] > 1) ? 1.f : 0.f;
        qinvI[tid] = g_invq[tid];
        qinvS[tid] = g_invq[32 + tid];
    }
    __syncthreads();

    // ---- phase 1: gather E (both tiles) -> bf16 + invI ----
    for (int sg = wid; sg < 256; sg += 16) {
        int tl = sg >> 7, s = sg & 127;
        const float4* row = (const float4*)(embeds + (size_t)ids[sg] * NE);
        __nv_bfloat16* dst = Eb + tl * (TILE_B / 2) + s * EROW;
        float ss = 0.f;
        for (int e4 = lane; e4 < 75; e4 += 32) {
            float4 v = row[e4];
            *(uint2*)&dst[e4 * 4] = pack_bf16x4(v);
            ss += v.x * v.x + v.y * v.y + v.z * v.z + v.w * v.w;
        }
        #pragma unroll
        for (int o = 16; o > 0; o >>= 1) ss += __shfl_down_sync(0xffffffffu, ss, o);
        if (lane == 0) invI_s[sg] = rsqrtf(ss);
    }

    uint32_t ea_u = smem_u32(Eb) + sent * TILE_B;
    uint32_t ws_u = smem_u32(Ws);
    uint32_t wbase = (uint32_t)(fhalf * 32);

    // ---- phase 2: conv norms; 15 rounds (5 slab64 x 3 taps) ----
    float cc[2][4][4];
    float rs[2][2] = {{0.f, 0.f}, {0.f, 0.f}};
    for (int r = 0; r < 15; r++) {
        int slab64 = r / 3, tap = r % 3;
        __syncthreads();                       // prior mma done reading Ws
        stage_w64(filters, Ws, slab64, tap, tid);
        __syncthreads();
        if (tap == 0) {
            #pragma unroll
            for (int rt = 0; rt < 2; rt++)
                #pragma unroll
                for (int j = 0; j < 4; j++)
                    #pragma unroll
                    for (int x = 0; x < 4; x++) cc[rt][j][x] = 0.f;
        }
        for (int ec = 0; ec < 19; ec++) {
            uint32_t a00, a01, a02, a03, a10, a11, a12, a13;
            uint32_t aaddr0 = ea_u + (uint32_t)(((r0 + tap + arow) * EROW + ec * 16 + acol) * 2);
            uint32_t aaddr1 = ea_u + (uint32_t)(((r0 + 16 + tap + arow) * EROW + ec * 16 + acol) * 2);
            LDSM_X4(a00, a01, a02, a03, aaddr0);
            LDSM_X4(a10, a11, a12, a13, aaddr1);
            #pragma unroll
            for (int np = 0; np < 2; np++) {
                uint32_t b0, b1, b2, b3;
                uint32_t baddr = ws_u + (uint32_t)(((wbase + np * 16 + brow) * EROW + ec * 16 + bcol) * 2);
                LDSM_X4(b0, b1, b2, b3, baddr);
                MMA16816(cc[0][np * 2], a00, a01, a02, a03, b0, b1);
                MMA16816(cc[0][np * 2 + 1], a00, a01, a02, a03, b2, b3);
                MMA16816(cc[1][np * 2], a10, a11, a12, a13, b0, b1);
                MMA16816(cc[1][np * 2 + 1], a10, a11, a12, a13, b2, b3);
            }
        }
        if (tap == 2) {
            #pragma unroll
            for (int rt = 0; rt < 2; rt++)
                #pragma unroll
                for (int j = 0; j < 4; j++) {
                    rs[rt][0] += cc[rt][j][0] * cc[rt][j][0] + cc[rt][j][1] * cc[rt][j][1];
                    rs[rt][1] += cc[rt][j][2] * cc[rt][j][2] + cc[rt][j][3] * cc[rt][j][3];
                }
        }
    }
    #pragma unroll
    for (int rt = 0; rt < 2; rt++)
        #pragma unroll
        for (int h = 0; h < 2; h++) {
            rs[rt][h] += __shfl_xor_sync(0xffffffffu, rs[rt][h], 1);
            rs[rt][h] += __shfl_xor_sync(0xffffffffu, rs[rt][h], 2);
        }
    if (c4 == 0) {
        #pragma unroll
        for (int rt = 0; rt < 2; rt++) {
            int row0 = r0 + rt * 16 + g2;
            pnorm[(sent * 128 + row0) * 2 + fhalf] = rs[rt][0];
            pnorm[(sent * 128 + row0 + 8) * 2 + fhalf] = rs[rt][1];
        }
    }
    __syncthreads();
    if (tid < 256) invS_s[tid] = rsqrtf(pnorm[2 * tid] + pnorm[2 * tid + 1]);

    // ---- phase 3: P = E @ B2t; 2 rounds of 64-wide B2 slabs ----
    float pa[2][8][4];
    #pragma unroll
    for (int rd = 0; rd < 2; rd++)
        #pragma unroll
        for (int j = 0; j < 8; j++)
            #pragma unroll
            for (int x = 0; x < 4; x++) pa[rd][j][x] = 0.f;

    for (int rnd = 0; rnd < 2; rnd++) {
        __syncthreads();
        stage_b64(Ws, rnd, tid);
        __syncthreads();
        for (int ec = 0; ec < 19; ec++) {
            uint32_t a00, a01, a02, a03, a10, a11, a12, a13;
            uint32_t aaddr0 = ea_u + (uint32_t)(((r0 + arow) * EROW + ec * 16 + acol) * 2);
            uint32_t aaddr1 = ea_u + (uint32_t)(((r0 + 16 + arow) * EROW + ec * 16 + acol) * 2);
            LDSM_X4(a00, a01, a02, a03, aaddr0);
            LDSM_X4(a10, a11, a12, a13, aaddr1);
            #pragma unroll
            for (int np = 0; np < 2; np++) {
                uint32_t b0, b1, b2, b3;
                uint32_t baddr = ws_u + (uint32_t)(((wbase + np * 16 + brow) * EROW + ec * 16 + bcol) * 2);
                LDSM_X4(b0, b1, b2, b3, baddr);
                MMA16816(pa[rnd][np * 2], a00, a01, a02, a03, b0, b1);
                MMA16816(pa[rnd][np * 2 + 1], a00, a01, a02, a03, b2, b3);
                MMA16816(pa[rnd][4 + np * 2], a10, a11, a12, a13, b0, b1);
                MMA16816(pa[rnd][4 + np * 2 + 1], a10, a11, a12, a13, b2, b3);
            }
        }
    }
    __syncthreads();   // all E reads done; safe to overwrite with P

    float* P = Pbase + sent * PTILE;
    #pragma unroll
    for (int rnd = 0; rnd < 2; rnd++)
        #pragma unroll
        for (int rt = 0; rt < 2; rt++)
            #pragma unroll
            for (int np = 0; np < 2; np++)
                #pragma unroll
                for (int j = 0; j < 2; j++) {
                    float* f = pa[rnd][rt * 4 + np * 2 + j];
                    int c = rnd * 64 + fhalf * 32 + np * 16 + j * 8 + c4 * 2;
                    int s = r0 + rt * 16 + g2;
                    P[c * PSTRIDE + s] = f[0];
                    P[(c + 1) * PSTRIDE + s] = f[1];
                    P[c * PSTRIDE + s + 8] = f[2];
                    P[(c + 1) * PSTRIDE + s + 8] = f[3];
                }
    __syncthreads();

    // ---- phase 4/5: sims -> top-5 -> logit ----
    float w0 = lin_w[0], w1 = lin_w[1], w2 = lin_w[2];
    float w3 = lin_w[3], w4 = lin_w[4], w5 = lin_w[5], b0 = lin_b[0];
    {
        int sb = sent * 128;
        float* Ps = Pbase + sent * PTILE;
        for (int qq = ww * 4; qq < ww * 4 + 4; qq++) {
            float qi = qinvI[qq], qs = qinvS[qq], qm = qmf[qq];
            float vI[4], vS[4], vO[4];
            #pragma unroll
            for (int j = 0; j < 4; j++) {
                int s = lane + 32 * j;
                float a = Ps[qq * PSTRIDE + s] * qi * invI_s[sb + s] * qm;
                if (ids[sb + s] <= 1) a = 0.f;
                vI[j] = a;
                float num = Ps[(32 + qq) * PSTRIDE + s];
                if (s + 1 < SLEN) num += Ps[(64 + qq) * PSTRIDE + s + 1];
                if (s + 2 < SLEN) num += Ps[(96 + qq) * PSTRIDE + s + 2];
                vS[j] = num * qs * invS_s[sb + s];
                vO[j] = dsim[((size_t)(m0 + sent) * QLEN + qq) * SLEN + s];
            }
            float mI, aI, mS, aS, mO, aO;
            top5v(vI[0], vI[1], vI[2], vI[3], lane, mI, aI);
            top5v(vS[0], vS[1], vS[2], vS[3], lane, mS, aS);
            top5v(vO[0], vO[1], vO[2], vO[3], lane, mO, aO);
            float logit = b0 + w0 * mI + w1 * aI + w2 * mS + w3 * aS + w4 * mO + w5 * aO;
            if (lane == 0) slog[sent * 32 + qq] = 1.f / (1.f + expf(-logit));
        }
    }
    __syncthreads();

    if (wid < 2) {
        float v = slog[wid * 32 + lane];
        #pragma unroll
        for (int o = 16; o > 0; o >>= 1) v += __shfl_down_sync(0xffffffffu, v, o);
        if (lane == 0) out[2 * bn + wid] = v * (1.0f / QLEN);
    }
}

// ---------------------------------------------------------------------------
// Input order: embeds, filters, lin_w, lin_b, question, doc1, doc2,
//              doc1_sim, doc2_sim
extern "C" void kernel_launch(void* const* d_in, const int* in_sizes, int n_in,
                              void* d_out, int out_size) {
    const float* embeds   = (const float*)d_in[0];
    const float* filters  = (const float*)d_in[1];
    const float* lin_w    = (const float*)d_in[2];
    const float* lin_b    = (const float*)d_in[3];
    const int*   question = (const int*)d_in[4];
    const int*   doc1     = (const int*)d_in[5];
    const int*   doc2     = (const int*)d_in[6];
    const float* doc1_sim = (const float*)d_in[7];
    const float* doc2_sim = (const float*)d_in[8];
    float* out = (float*)d_out;

    cudaFuncSetAttribute(k_doc, cudaFuncAttributeMaxDynamicSharedMemorySize, DOC_SMEM);

    k_prep_q<<<QLEN, 128>>>(embeds, question);
    k_qconv<<<dim3(QLEN, 3), 128>>>(filters);
    k_buildU<<<dim3(96, 3), 128>>>(filters);

    k_doc<<<NSENT, 512, DOC_SMEM>>>(embeds, filters, doc1, doc2,
                                    doc1_sim, doc2_sim, question,
                                    lin_w, lin_b, out);
}